// round 5
// baseline (speedup 1.0000x reference)
#include <cuda_runtime.h>
#include <math.h>

// ---------------------------------------------------------------------------
// Problem constants
// ---------------------------------------------------------------------------
constexpr int H_    = 93;
constexpr int W_    = 44;
constexpr int HW_   = H_ * W_;      // 4092
constexpr int B_    = 8;
constexpr int HID_  = 128;
constexpr int LAT_  = 1024;
constexpr int MAXN_ = 24;
constexpr int OFF1  = B_ * HW_ * 2; // 65472  (start of mask_indices, as float)
constexpr int OFF2  = 2 * OFF1;     // 130944 (start of valid_mask, as float)
constexpr int NBORD = 1032;         // border positions (4-wide frame)
constexpr int NCHUNK = 16;          // kD position chunks per batch
constexpr int PCHUNK = 65;          // positions per chunk (16*65 >= 1032)

// ---------------------------------------------------------------------------
// Scratch (__device__ globals: no allocation allowed)
// ---------------------------------------------------------------------------
__device__ float g_lc  [B_ * HID_];           // gelu(latent @ Wl + bl)
__device__ float g_G9  [B_ * 9 * HID_];       // 9-class post GN+gelu
__device__ float g_F25 [B_ * 25 * HID_];      // 25-class feats (post conv2+gelu)
__device__ float g_s25 [B_ * 25];             // class attention scores
__device__ float g_Y   [B_ * 25 * HID_];      // F25 @ W1[:128]
__device__ float g_base[B_ * HID_];           // latent_cond @ W1[128:] + b1
__device__ float g_preds[B_ * HW_ * 2];       // border-position predictions

__device__ __forceinline__ float gelu_(float x) {
    return 0.5f * x * (1.0f + erff(x * 0.70710678118654752440f));
}

// rowmap[out_row_class][tap] -> input row-class (0=top,1=mid,2=bot), -1 = OOB
__constant__ int c_map[5][3] = {
    {-1, 0, 1},  // r = 0
    { 0, 1, 1},  // r = 1
    { 1, 1, 1},  // interior
    { 1, 1, 2},  // r = H-2
    { 1, 2,-1},  // r = H-1
};

// ---------------------------------------------------------------------------
// KA: per-batch fused chain:  lc = gelu(latent@Wl+bl)
//                             T[t] = lc @ Wt[t]
//                             G9  = gelu(GN(conv_transpose classes))
//     grid(B), block(1024)
// ---------------------------------------------------------------------------
__global__ __launch_bounds__(1024) void kA(const float* __restrict__ lat,
                                           const float* __restrict__ Wl,
                                           const float* __restrict__ bl,
                                           const float* __restrict__ Wt,
                                           const float* __restrict__ bt,
                                           const float* __restrict__ g1,
                                           const float* __restrict__ b1g) {
    int b = blockIdx.x, tid = threadIdx.x;
    __shared__ float ls[LAT_];
    __shared__ float red[1024];
    __shared__ float s_lc[HID_];
    __shared__ float s_T[9 * HID_];

    // --- latent GEMV, 8-way i-split ---
    ls[tid] = lat[b * LAT_ + tid];
    __syncthreads();
    int o = tid & 127, s = tid >> 7;
    {
        const float* w = Wl + (size_t)(s * 128) * HID_ + o;
        float acc = 0.f;
        #pragma unroll 8
        for (int i = 0; i < 128; i++) acc = fmaf(ls[s * 128 + i], w[i * HID_], acc);
        red[tid] = acc;
    }
    __syncthreads();
    for (int st = 4; st >= 1; st >>= 1) {
        if (s < st) red[tid] += red[tid + st * 128];
        __syncthreads();
    }
    if (tid < HID_) {
        float v = gelu_(red[tid] + bl[tid]);
        s_lc[tid] = v;
        g_lc[b * HID_ + tid] = v;
    }
    __syncthreads();

    // --- 9 taps: T[t,o] = lc . Wt[t,:,o] ---
    for (int idx = tid; idx < 9 * HID_; idx += 1024) {
        int t = idx >> 7, oo = idx & 127;
        const float* w = Wt + (size_t)t * HID_ * HID_ + oo;
        float acc = 0.f;
        #pragma unroll 8
        for (int i = 0; i < HID_; i++) acc = fmaf(s_lc[i], w[i * HID_], acc);
        s_T[idx] = acc;
    }
    __syncthreads();

    // --- 9-class values + area-weighted GroupNorm(8 groups of 16ch) + gelu ---
    if (tid < HID_) {
        float Tl[9];
        for (int t = 0; t < 9; t++) Tl[t] = s_T[t * HID_ + tid];
        float btv = bt[tid];

        float c9[9];
        for (int rc = 0; rc < 3; rc++)
            for (int cc = 0; cc < 3; cc++) {
                float sum = btv;
                for (int kh = 0; kh < 3; kh++) {
                    if ((rc == 0 && kh == 0) || (rc == 2 && kh == 2)) continue;
                    for (int kw = 0; kw < 3; kw++) {
                        if ((cc == 0 && kw == 0) || (cc == 2 && kw == 2)) continue;
                        sum += Tl[kh * 3 + kw];
                    }
                }
                c9[rc * 3 + cc] = sum;
            }

        const float rowcnt[3] = {1.f, (float)(H_ - 2), 1.f};
        const float colcnt[3] = {1.f, (float)(W_ - 2), 1.f};
        float area[9];
        for (int rc = 0; rc < 3; rc++)
            for (int cc = 0; cc < 3; cc++)
                area[rc * 3 + cc] = rowcnt[rc] * colcnt[cc];

        const float inv = 1.0f / (16.0f * (float)HW_);
        float sm = 0.f;
        for (int k = 0; k < 9; k++) sm += area[k] * c9[k];
        for (int off = 8; off >= 1; off >>= 1) sm += __shfl_xor_sync(0xffffffffu, sm, off);
        float mean = sm * inv;

        float d = 0.f;
        for (int k = 0; k < 9; k++) { float t = c9[k] - mean; d += area[k] * t * t; }
        for (int off = 8; off >= 1; off >>= 1) d += __shfl_xor_sync(0xffffffffu, d, off);
        float rstd = rsqrtf(d * inv + 1e-5f);

        float ga = g1[tid], be = b1g[tid];
        for (int k = 0; k < 9; k++)
            g_G9[(b * 9 + k) * HID_ + tid] = gelu_((c9[k] - mean) * rstd * ga + be);
    }
}

// ---------------------------------------------------------------------------
// KB: 25-class second conv + gelu; also zeroes the output buffer
//     grid(25, 8) ; block 512 = 16 o x 8 b x 4 s(i-split)
// ---------------------------------------------------------------------------
__global__ __launch_bounds__(512) void kB(const float* __restrict__ Wc,
                                          const float* __restrict__ bc,
                                          float* __restrict__ out,
                                          int out_n4) {
    int cls = blockIdx.x;
    int orc = cls / 5, occ = cls % 5;
    int tid = threadIdx.x;
    int oo = tid & 15, b = (tid >> 4) & 7, s = tid >> 7;
    int o  = blockIdx.y * 16 + oo;

    // --- zero output buffer (spread across the 200 blocks) ---
    {
        int bid = blockIdx.y * 25 + blockIdx.x;
        float4 z = make_float4(0.f, 0.f, 0.f, 0.f);
        for (int i = bid * 512 + tid; i < out_n4; i += 200 * 512)
            ((float4*)out)[i] = z;
    }

    __shared__ float gs[B_ * 9 * HID_];   // 36 KB: all batches' 9-class feats
    __shared__ float sp[512];
    for (int i = tid; i < B_ * 9 * HID_; i += 512) gs[i] = g_G9[i];
    __syncthreads();

    float acc = 0.f;
    for (int kh = 0; kh < 3; kh++) {
        int ir = c_map[orc][kh];
        if (ir < 0) continue;
        for (int kw = 0; kw < 3; kw++) {
            int ic = c_map[occ][kw];
            if (ic < 0) continue;
            const float* gv = gs + (b * 9 + ir * 3 + ic) * HID_ + s * 32;
            const float* w  = Wc + (size_t)(kh * 3 + kw) * HID_ * HID_ + (size_t)(s * 32) * HID_ + o;
            #pragma unroll
            for (int i = 0; i < 32; i++) acc = fmaf(gv[i], w[i * HID_], acc);
        }
    }
    sp[tid] = acc;
    __syncthreads();
    if (s < 2) sp[tid] += sp[tid + 256];
    __syncthreads();
    if (s == 0) {
        float v = sp[tid] + sp[tid + 128] + bc[o];
        g_F25[(b * 25 + cls) * HID_ + o] = gelu_(v);
    }
}

// ---------------------------------------------------------------------------
// KC: cls<25 : Y[b,cls,:] = F25@W1[:128], s25 = F25.Wa + ba
//     cls==25: base[b,:]  = lc@W1[128:] + b1
//     grid(B, 26), block(HID)
// ---------------------------------------------------------------------------
__global__ void kC(const float* __restrict__ Wa,
                   const float* __restrict__ ba,
                   const float* __restrict__ W1,
                   const float* __restrict__ b1) {
    int b = blockIdx.x, cls = blockIdx.y, o = threadIdx.x;
    __shared__ float fs[HID_];
    __shared__ float red[4];

    if (cls == 25) {
        fs[o] = g_lc[b * HID_ + o];
        __syncthreads();
        float acc = b1[o];
        const float* w = W1 + (size_t)HID_ * HID_ + o;
        #pragma unroll 8
        for (int i = 0; i < HID_; i++) acc = fmaf(fs[i], w[i * HID_], acc);
        g_base[b * HID_ + o] = acc;
        return;
    }

    fs[o] = g_F25[(b * 25 + cls) * HID_ + o];
    __syncthreads();

    float a = 0.f;
    #pragma unroll 8
    for (int i = 0; i < HID_; i++) a = fmaf(fs[i], W1[i * HID_ + o], a);
    g_Y[(b * 25 + cls) * HID_ + o] = a;

    float sv = fs[o] * Wa[o];
    for (int off = 16; off >= 1; off >>= 1) sv += __shfl_xor_sync(0xffffffffu, sv, off);
    if ((o & 31) == 0) red[o >> 5] = sv;
    __syncthreads();
    if (o == 0) g_s25[b * 25 + cls] = red[0] + red[1] + red[2] + red[3] + ba[0];
}

// ---------------------------------------------------------------------------
// KD: border-position masked-neighbor attention + MLP -> g_preds
//     grid(B, NCHUNK), block(256): Y/base/s25/W2 cached in smem,
//     each of 8 warps loops over positions of the chunk
// ---------------------------------------------------------------------------
__global__ __launch_bounds__(256) void kD(const int* __restrict__ mask,
                                          const int* __restrict__ nidx,
                                          const int* __restrict__ ncnt,
                                          const float* __restrict__ W2,
                                          const float* __restrict__ b2) {
    int b = blockIdx.x;
    int chunk = blockIdx.y;
    int tid = threadIdx.x;
    int warp = tid >> 5, lane = tid & 31;

    __shared__ float sY[25 * HID_];     // 12.8 KB
    __shared__ float sBase[HID_];
    __shared__ float sS25[32];
    __shared__ float sW2[2 * HID_];
    __shared__ float wc[8][25];

    for (int i = tid; i < 25 * HID_; i += 256) sY[i] = g_Y[b * 25 * HID_ + i];
    if (tid < HID_)            sBase[tid] = g_base[b * HID_ + tid];
    else if (tid < HID_ + 25)  sS25[tid - HID_] = g_s25[b * 25 + (tid - HID_)];
    sW2[tid] = W2[tid];   // 256 floats exactly
    __syncthreads();

    float b20 = b2[0], b21 = b2[1];
    const int* maskb = mask + b * HW_;

    int jend = min(NBORD, (chunk + 1) * PCHUNK);
    for (int j = chunk * PCHUNK + warp; j < jend; j += 8) {
        // border index -> (r, c)
        int r, c;
        if (j < 176)      { r = j / 44;                 c = j % 44; }
        else if (j < 352) { int j2 = j - 176; r = 89 + j2 / 44; c = j2 % 44; }
        else              { int j3 = j - 352; r = 4 + j3 / 8;
                            int k = j3 % 8; c = (k < 4) ? k : 36 + k; }
        int p = r * W_ + c;

        if (lane < 25) wc[warp][lane] = 0.f;
        __syncwarp();

        bool has = lane < MAXN_;
        float logit = -3.0e38f;
        int cls = 0;
        if (has) {
            int idx = nidx[p * MAXN_ + lane];
            int rr = idx / W_, c2 = idx % W_;
            int rc = (rr == 0) ? 0 : (rr == 1) ? 1 : (rr == H_ - 2) ? 3 : (rr == H_ - 1) ? 4 : 2;
            int cc = (c2 == 0) ? 0 : (c2 == 1) ? 1 : (c2 == W_ - 2) ? 3 : (c2 == W_ - 1) ? 4 : 2;
            cls = rc * 5 + cc;
            bool valid = (lane < ncnt[p]) && (maskb[idx] == 0);
            logit = valid ? sS25[cls] : -10000.0f;
        }
        float m = logit;
        for (int off = 16; off >= 1; off >>= 1) m = fmaxf(m, __shfl_xor_sync(0xffffffffu, m, off));
        float e = has ? expf(logit - m) : 0.f;
        float se = e;
        for (int off = 16; off >= 1; off >>= 1) se += __shfl_xor_sync(0xffffffffu, se, off);
        float wgt = e / se;
        if (has && wgt != 0.f) atomicAdd(&wc[warp][cls], wgt);
        __syncwarp();

        float p0 = 0.f, p1 = 0.f;
        #pragma unroll
        for (int k = 0; k < 4; k++) {
            int o = lane + 32 * k;
            float acc = sBase[o];
            #pragma unroll
            for (int cl = 0; cl < 25; cl++)
                acc = fmaf(wc[warp][cl], sY[cl * HID_ + o], acc);
            float h = gelu_(acc);
            p0 = fmaf(h, sW2[o * 2], p0);
            p1 = fmaf(h, sW2[o * 2 + 1], p1);
        }
        for (int off = 16; off >= 1; off >>= 1) {
            p0 += __shfl_xor_sync(0xffffffffu, p0, off);
            p1 += __shfl_xor_sync(0xffffffffu, p1, off);
        }
        if (lane == 0) {
            g_preds[(b * HW_ + p) * 2]     = p0 + b20;
            g_preds[(b * HW_ + p) * 2 + 1] = p1 + b21;
        }
        __syncwarp();
    }
}

// ---------------------------------------------------------------------------
// KE: compute Pint(b), per-row prefix scan, scatter packed outputs
//     grid(B), block(1024)   (zeroing moved to kB)
// ---------------------------------------------------------------------------
__global__ __launch_bounds__(1024) void kE(const int* __restrict__ mask,
                                           const float* __restrict__ W2,
                                           const float* __restrict__ b2,
                                           float* __restrict__ out) {
    int b = blockIdx.x, t = threadIdx.x;
    int lane = t & 31, warp = t >> 5;
    __shared__ int wsum[32];
    __shared__ float sP[2];

    // --- interior prediction: Pint = MLP(Y[cls12] + base) (warp 0) ---
    if (t < 32) {
        float p0 = 0.f, p1 = 0.f;
        for (int k = 0; k < 4; k++) {
            int o = t + 32 * k;
            float h = gelu_(g_Y[(b * 25 + 12) * HID_ + o] + g_base[b * HID_ + o]);
            p0 = fmaf(h, W2[o * 2], p0);
            p1 = fmaf(h, W2[o * 2 + 1], p1);
        }
        for (int off = 16; off >= 1; off >>= 1) {
            p0 += __shfl_xor_sync(0xffffffffu, p0, off);
            p1 += __shfl_xor_sync(0xffffffffu, p1, off);
        }
        if (t == 0) { sP[0] = p0 + b2[0]; sP[1] = p1 + b2[1]; }
    }

    // --- per-row scan of mask ---
    int base = t * 4;
    int m[4], loc[4];
    int s = 0;
    for (int j = 0; j < 4; j++) {
        int p = base + j;
        int mm = (p < HW_) ? (mask[b * HW_ + p] > 0) : 0;
        m[j] = mm; loc[j] = s; s += mm;
    }
    int v = s;
    for (int off = 1; off < 32; off <<= 1) {
        int u = __shfl_up_sync(0xffffffffu, v, off);
        if (lane >= off) v += u;
    }
    if (lane == 31) wsum[warp] = v;
    __syncthreads();                       // also publishes Pint
    if (warp == 0) {
        int wv = wsum[lane];
        for (int off = 1; off < 32; off <<= 1) {
            int u = __shfl_up_sync(0xffffffffu, wv, off);
            if (lane >= off) wv += u;
        }
        wsum[lane] = wv;
    }
    __syncthreads();
    int excl = (v - s) + (warp > 0 ? wsum[warp - 1] : 0);

    float Pi0 = sP[0], Pi1 = sP[1];
    for (int j = 0; j < 4; j++) {
        if (m[j]) {
            int p = base + j;
            int slot = excl + loc[j];
            int r = p / W_, c = p % W_;
            bool interior = (r >= 4 && r <= H_ - 5 && c >= 4 && c <= W_ - 5);
            float v0 = interior ? Pi0 : g_preds[(b * HW_ + p) * 2];
            float v1 = interior ? Pi1 : g_preds[(b * HW_ + p) * 2 + 1];
            out[(b * HW_ + slot) * 2]            = v0;
            out[(b * HW_ + slot) * 2 + 1]        = v1;
            out[OFF1 + (b * HW_ + slot) * 2]     = (float)r;
            out[OFF1 + (b * HW_ + slot) * 2 + 1] = (float)c;
            out[OFF2 + b * HW_ + slot]           = 1.0f;
        }
    }
}

// ---------------------------------------------------------------------------
// kernel_launch
// Inputs: face_tensor, latent_token, mask_2d, nbr_indices, nbr_counts,
//         Wl, bl, Wt, bt, g1, b1g, Wc, bc, Wa, ba, W1, b1, W2, b2
// ---------------------------------------------------------------------------
extern "C" void kernel_launch(void* const* d_in, const int* in_sizes, int n_in,
                              void* d_out, int out_size) {
    const float* latent = (const float*)d_in[1];
    const int*   mask   = (const int*)  d_in[2];
    const int*   nidx   = (const int*)  d_in[3];
    const int*   ncnt   = (const int*)  d_in[4];
    const float* Wl = (const float*)d_in[5];
    const float* bl = (const float*)d_in[6];
    const float* Wt = (const float*)d_in[7];
    const float* bt = (const float*)d_in[8];
    const float* g1 = (const float*)d_in[9];
    const float* b1g= (const float*)d_in[10];
    const float* Wc = (const float*)d_in[11];
    const float* bc = (const float*)d_in[12];
    const float* Wa = (const float*)d_in[13];
    const float* ba = (const float*)d_in[14];
    const float* W1 = (const float*)d_in[15];
    const float* b1 = (const float*)d_in[16];
    const float* W2 = (const float*)d_in[17];
    const float* b2 = (const float*)d_in[18];

    kA<<<B_, 1024>>>(latent, Wl, bl, Wt, bt, g1, b1g);
    { dim3 g(25, 8); kB<<<g, 512>>>(Wc, bc, (float*)d_out, out_size / 4); }
    { dim3 g(B_, 26); kC<<<g, HID_>>>(Wa, ba, W1, b1); }
    { dim3 g(B_, NCHUNK); kD<<<g, 256>>>(mask, nidx, ncnt, W2, b2); }
    kE<<<B_, 1024>>>(mask, W2, b2, (float*)d_out);
}

// round 6
// speedup vs baseline: 1.2966x; 1.2966x over previous
#include <cuda_runtime.h>
#include <math.h>

// ---------------------------------------------------------------------------
// Problem constants
// ---------------------------------------------------------------------------
constexpr int H_    = 93;
constexpr int W_    = 44;
constexpr int HW_   = H_ * W_;      // 4092
constexpr int B_    = 8;
constexpr int HID_  = 128;
constexpr int LAT_  = 1024;
constexpr int MAXN_ = 24;
constexpr int OFF1  = B_ * HW_ * 2; // 65472  (mask_indices start, as float)
constexpr int OFF2  = 2 * OFF1;     // 130944 (valid_mask start, as float)
constexpr int NBORD = 1032;         // border positions (4-wide frame)
constexpr int NT4   = 8256;         // NBORD * B_ warp-tasks for phase 4

// ---------------------------------------------------------------------------
// Scratch (__device__ globals: no allocation allowed)
// ---------------------------------------------------------------------------
__device__ __align__(16) float g_lc  [B_ * HID_];
__device__ __align__(16) float g_G9  [B_ * 9 * HID_];
__device__ __align__(16) float g_F25 [B_ * 25 * HID_];
__device__ __align__(16) float g_s25 [B_ * 25];
__device__ __align__(16) float g_Y   [B_ * 25 * HID_];
__device__ __align__(16) float g_base[B_ * HID_];
__device__ __align__(16) float g_preds[B_ * HW_ * 2];
__device__ unsigned g_bar;          // monotonic barrier counter (zero-init once)

__device__ __forceinline__ float gelu_(float x) {
    return 0.5f * x * (1.0f + erff(x * 0.70710678118654752440f));
}

// rowmap[out_row_class][tap] -> input row-class (0=top,1=mid,2=bot), -1 = OOB
__constant__ int c_map[5][3] = {
    {-1, 0, 1}, { 0, 1, 1}, { 1, 1, 1}, { 1, 1, 2}, { 1, 2,-1},
};

// ---------------------------------------------------------------------------
// Software grid barrier. grid == #SMs and occupancy>=1 => all blocks resident.
// Monotonic counter; each epoch releases at the next multiple of gridDim.x,
// so it stays correct across arbitrarily many graph replays.
// ---------------------------------------------------------------------------
__device__ __forceinline__ void grid_bar() {
    __syncthreads();
    if (threadIdx.x == 0) {
        __threadfence();
        unsigned old = atomicAdd(&g_bar, 1u);
        unsigned target = old - (old % gridDim.x) + gridDim.x;
        while (*(volatile unsigned*)&g_bar < target) { __nanosleep(32); }
        __threadfence();
    }
    __syncthreads();
}

// ---------------------------------------------------------------------------
// Shared memory union across phases (max member = 40 KB < 48 KB static limit)
// ---------------------------------------------------------------------------
union SmemU {
    struct { float ls[LAT_]; float red[1024]; float s_lc[HID_]; float s_T[9 * HID_]; } p1;
    struct { float gs[B_ * 9 * HID_]; float sp[1024]; } p2;
    struct { float fs[8][HID_]; float red[8][4]; } p3;
    struct { float wc[32][25]; } p4;
    struct { int wsum[32]; float sP[2]; } p5;
};

// ---------------------------------------------------------------------------
// The one persistent kernel
// ---------------------------------------------------------------------------
__global__ __launch_bounds__(1024, 1) void kFused(
    const float* __restrict__ lat,  const int* __restrict__ mask,
    const int* __restrict__ nidx,   const int* __restrict__ ncnt,
    const float* __restrict__ Wl,   const float* __restrict__ bl,
    const float* __restrict__ Wt,   const float* __restrict__ bt,
    const float* __restrict__ g1,   const float* __restrict__ b1g,
    const float* __restrict__ Wc,   const float* __restrict__ bc,
    const float* __restrict__ Wa,   const float* __restrict__ ba,
    const float* __restrict__ W1,   const float* __restrict__ b1,
    const float* __restrict__ W2,   const float* __restrict__ b2,
    float* __restrict__ out,        int out_n4) {

    __shared__ SmemU su;
    const int tid  = threadIdx.x;
    const int blk  = blockIdx.x;
    const int grid = gridDim.x;

    // =====================================================================
    // Phase 1: blocks 0..7  -> lc, taps, GN  (batch = blk)
    //          blocks 8+    -> zero the output buffer
    // =====================================================================
    if (blk < 8) {
        const int b = blk;
        su.p1.ls[tid] = lat[b * LAT_ + tid];
        __syncthreads();
        int o = tid & 127, s = tid >> 7;
        {
            const float* w = Wl + (size_t)(s * 128) * HID_ + o;
            float acc = 0.f;
            #pragma unroll 8
            for (int i = 0; i < 128; i++) acc = fmaf(su.p1.ls[s * 128 + i], w[i * HID_], acc);
            su.p1.red[tid] = acc;
        }
        __syncthreads();
        for (int st = 4; st >= 1; st >>= 1) {
            if (s < st) su.p1.red[tid] += su.p1.red[tid + st * 128];
            __syncthreads();
        }
        if (tid < HID_) {
            float v = gelu_(su.p1.red[tid] + bl[tid]);
            su.p1.s_lc[tid] = v;
            g_lc[b * HID_ + tid] = v;
        }
        __syncthreads();

        for (int idx = tid; idx < 9 * HID_; idx += 1024) {
            int t = idx >> 7, oo = idx & 127;
            const float* w = Wt + (size_t)t * HID_ * HID_ + oo;
            float acc = 0.f;
            #pragma unroll 8
            for (int i = 0; i < HID_; i++) acc = fmaf(su.p1.s_lc[i], w[i * HID_], acc);
            su.p1.s_T[idx] = acc;
        }
        __syncthreads();

        if (tid < HID_) {
            float Tl[9];
            for (int t = 0; t < 9; t++) Tl[t] = su.p1.s_T[t * HID_ + tid];
            float btv = bt[tid];

            float c9[9];
            for (int rc = 0; rc < 3; rc++)
                for (int cc = 0; cc < 3; cc++) {
                    float sum = btv;
                    for (int kh = 0; kh < 3; kh++) {
                        if ((rc == 0 && kh == 0) || (rc == 2 && kh == 2)) continue;
                        for (int kw = 0; kw < 3; kw++) {
                            if ((cc == 0 && kw == 0) || (cc == 2 && kw == 2)) continue;
                            sum += Tl[kh * 3 + kw];
                        }
                    }
                    c9[rc * 3 + cc] = sum;
                }

            const float rowcnt[3] = {1.f, (float)(H_ - 2), 1.f};
            const float colcnt[3] = {1.f, (float)(W_ - 2), 1.f};
            float area[9];
            for (int rc = 0; rc < 3; rc++)
                for (int cc = 0; cc < 3; cc++)
                    area[rc * 3 + cc] = rowcnt[rc] * colcnt[cc];

            const float inv = 1.0f / (16.0f * (float)HW_);
            float sm = 0.f;
            for (int k = 0; k < 9; k++) sm += area[k] * c9[k];
            for (int off = 8; off >= 1; off >>= 1) sm += __shfl_xor_sync(0xffffffffu, sm, off);
            float mean = sm * inv;

            float d = 0.f;
            for (int k = 0; k < 9; k++) { float t = c9[k] - mean; d += area[k] * t * t; }
            for (int off = 8; off >= 1; off >>= 1) d += __shfl_xor_sync(0xffffffffu, d, off);
            float rstd = rsqrtf(d * inv + 1e-5f);

            float ga = g1[tid], be = b1g[tid];
            for (int k = 0; k < 9; k++)
                g_G9[(b * 9 + k) * HID_ + tid] = gelu_((c9[k] - mean) * rstd * ga + be);
        }
    } else {
        float4 z = make_float4(0.f, 0.f, 0.f, 0.f);
        for (int i = (blk - 8) * 1024 + tid; i < out_n4; i += (grid - 8) * 1024)
            ((float4*)out)[i] = z;
    }
    grid_bar();

    // =====================================================================
    // Phase 2: 25-class second conv + gelu. 200 tasks (cls x ogroup),
    //          2 tasks per block (two 512-thread halves sharing staged G9).
    // =====================================================================
    if (blk * 2 < 200) {
        for (int i = tid; i < B_ * 9 * HID_; i += 1024) su.p2.gs[i] = g_G9[i];
        __syncthreads();

        const int h = tid >> 9, tid5 = tid & 511;
        const int oo = tid5 & 15, b = (tid5 >> 4) & 7, s = tid5 >> 7;
        float* spH = su.p2.sp + h * 512;

        for (int base = blk * 2; base < 200; base += grid * 2) {
            int t   = base + h;           // < 200 (200 even)
            int cls = t % 25, og = t / 25;
            int o   = og * 16 + oo;
            int orc = cls / 5, occ = cls % 5;

            float acc = 0.f;
            for (int kh = 0; kh < 3; kh++) {
                int ir = c_map[orc][kh];
                if (ir < 0) continue;
                for (int kw = 0; kw < 3; kw++) {
                    int ic = c_map[occ][kw];
                    if (ic < 0) continue;
                    const float* gv = su.p2.gs + (b * 9 + ir * 3 + ic) * HID_ + s * 32;
                    const float* w  = Wc + (size_t)(kh * 3 + kw) * HID_ * HID_
                                         + (size_t)(s * 32) * HID_ + o;
                    #pragma unroll
                    for (int i = 0; i < 32; i++) acc = fmaf(gv[i], w[i * HID_], acc);
                }
            }
            spH[tid5] = acc;
            __syncthreads();
            if (s < 2) spH[tid5] += spH[tid5 + 256];
            __syncthreads();
            if (s == 0) {
                float v = spH[tid5] + spH[tid5 + 128] + bc[o];
                g_F25[(b * 25 + cls) * HID_ + o] = gelu_(v);
            }
            __syncthreads();
        }
    }
    grid_bar();

    // =====================================================================
    // Phase 3: 208 tasks (b x 26): cls<25 -> Y + s25 ; cls==25 -> base
    //          8 tasks per block (128-thread groups)
    // =====================================================================
    {
        const int g = tid >> 7, o = tid & 127;
        for (int base = blk * 8; base < 208; base += grid * 8) {
            int task = base + g;          // < 208 (208 % 8 == 0)
            int b = task / 26, cls = task % 26;

            su.p3.fs[g][o] = (cls < 25) ? g_F25[(b * 25 + cls) * HID_ + o]
                                        : g_lc[b * HID_ + o];
            __syncthreads();
            const float* fs = su.p3.fs[g];

            float sv = 0.f;
            if (cls < 25) {
                float a = 0.f;
                #pragma unroll 8
                for (int i = 0; i < HID_; i++) a = fmaf(fs[i], W1[i * HID_ + o], a);
                g_Y[(b * 25 + cls) * HID_ + o] = a;
                sv = fs[o] * Wa[o];
            } else {
                float acc = b1[o];
                const float* w = W1 + (size_t)HID_ * HID_ + o;
                #pragma unroll 8
                for (int i = 0; i < HID_; i++) acc = fmaf(fs[i], w[i * HID_], acc);
                g_base[b * HID_ + o] = acc;
            }
            for (int off = 16; off >= 1; off >>= 1) sv += __shfl_xor_sync(0xffffffffu, sv, off);
            if ((o & 31) == 0) su.p3.red[g][o >> 5] = sv;
            __syncthreads();
            if (cls < 25 && o == 0)
                g_s25[b * 25 + cls] = su.p3.red[g][0] + su.p3.red[g][1]
                                    + su.p3.red[g][2] + su.p3.red[g][3] + ba[0];
            __syncthreads();
        }
    }
    grid_bar();

    // =====================================================================
    // Phase 4: border attention + MLP. 8256 warp-tasks over all warps.
    //          lane owns 4 channels (float4 path).
    // =====================================================================
    {
        const int warp = tid >> 5, lane = tid & 31;
        const int gw = blk * 32 + warp;
        const int nwarp = grid * 32;
        float* wcw = su.p4.wc[warp];
        const float b20 = b2[0], b21 = b2[1];

        for (int task = gw; task < NT4; task += nwarp) {
            int j = task >> 3, b = task & 7;
            int r, c;
            if (j < 176)      { r = j / 44;                 c = j % 44; }
            else if (j < 352) { int j2 = j - 176; r = 89 + j2 / 44; c = j2 % 44; }
            else              { int j3 = j - 352; r = 4 + j3 / 8;
                                int k = j3 % 8; c = (k < 4) ? k : 36 + k; }
            int p = r * W_ + c;

            if (lane < 25) wcw[lane] = 0.f;
            __syncwarp();

            bool has = lane < MAXN_;
            float logit = -3.0e38f;
            int cls = 0;
            if (has) {
                int idx = nidx[p * MAXN_ + lane];
                int rr = idx / W_, c2 = idx % W_;
                int rc = (rr == 0) ? 0 : (rr == 1) ? 1 : (rr == H_ - 2) ? 3 : (rr == H_ - 1) ? 4 : 2;
                int cc = (c2 == 0) ? 0 : (c2 == 1) ? 1 : (c2 == W_ - 2) ? 3 : (c2 == W_ - 1) ? 4 : 2;
                cls = rc * 5 + cc;
                bool valid = (lane < ncnt[p]) && (mask[b * HW_ + idx] == 0);
                logit = valid ? g_s25[b * 25 + cls] : -10000.0f;
            }
            float m = logit;
            for (int off = 16; off >= 1; off >>= 1)
                m = fmaxf(m, __shfl_xor_sync(0xffffffffu, m, off));
            float e = has ? expf(logit - m) : 0.f;
            float se = e;
            for (int off = 16; off >= 1; off >>= 1) se += __shfl_xor_sync(0xffffffffu, se, off);
            float wgt = e / se;
            if (has && wgt != 0.f) atomicAdd(&wcw[cls], wgt);
            __syncwarp();

            float4 acc = *(const float4*)&g_base[b * HID_ + lane * 4];
            #pragma unroll
            for (int cl = 0; cl < 25; cl++) {
                float wv = wcw[cl];
                if (wv != 0.f) {
                    float4 y = *(const float4*)&g_Y[(b * 25 + cl) * HID_ + lane * 4];
                    acc.x = fmaf(wv, y.x, acc.x);
                    acc.y = fmaf(wv, y.y, acc.y);
                    acc.z = fmaf(wv, y.z, acc.z);
                    acc.w = fmaf(wv, y.w, acc.w);
                }
            }
            float hx = gelu_(acc.x), hy = gelu_(acc.y), hz = gelu_(acc.z), hw = gelu_(acc.w);
            float4 w2a = *(const float4*)&W2[lane * 8];
            float4 w2b = *(const float4*)&W2[lane * 8 + 4];
            float p0 = hx * w2a.x + hy * w2a.z + hz * w2b.x + hw * w2b.z;
            float p1 = hx * w2a.y + hy * w2a.w + hz * w2b.y + hw * w2b.w;
            for (int off = 16; off >= 1; off >>= 1) {
                p0 += __shfl_xor_sync(0xffffffffu, p0, off);
                p1 += __shfl_xor_sync(0xffffffffu, p1, off);
            }
            if (lane == 0) {
                g_preds[(b * HW_ + p) * 2]     = p0 + b20;
                g_preds[(b * HW_ + p) * 2 + 1] = p1 + b21;
            }
            __syncwarp();
        }
    }
    grid_bar();

    // =====================================================================
    // Phase 5: blocks 0..7 -> Pint + per-row scan + packed scatter
    // =====================================================================
    if (blk < 8) {
        const int b = blk, t = tid;
        const int lane = t & 31, warp = t >> 5;

        if (t < 32) {
            float p0 = 0.f, p1 = 0.f;
            for (int k = 0; k < 4; k++) {
                int o = t + 32 * k;
                float h = gelu_(g_Y[(b * 25 + 12) * HID_ + o] + g_base[b * HID_ + o]);
                p0 = fmaf(h, W2[o * 2], p0);
                p1 = fmaf(h, W2[o * 2 + 1], p1);
            }
            for (int off = 16; off >= 1; off >>= 1) {
                p0 += __shfl_xor_sync(0xffffffffu, p0, off);
                p1 += __shfl_xor_sync(0xffffffffu, p1, off);
            }
            if (t == 0) { su.p5.sP[0] = p0 + b2[0]; su.p5.sP[1] = p1 + b2[1]; }
        }

        int base = t * 4;
        int m[4], loc[4];
        int s = 0;
        for (int j = 0; j < 4; j++) {
            int p = base + j;
            int mm = (p < HW_) ? (mask[b * HW_ + p] > 0) : 0;
            m[j] = mm; loc[j] = s; s += mm;
        }
        int v = s;
        for (int off = 1; off < 32; off <<= 1) {
            int u = __shfl_up_sync(0xffffffffu, v, off);
            if (lane >= off) v += u;
        }
        if (lane == 31) su.p5.wsum[warp] = v;
        __syncthreads();
        if (warp == 0) {
            int wv = su.p5.wsum[lane];
            for (int off = 1; off < 32; off <<= 1) {
                int u = __shfl_up_sync(0xffffffffu, wv, off);
                if (lane >= off) wv += u;
            }
            su.p5.wsum[lane] = wv;
        }
        __syncthreads();
        int excl = (v - s) + (warp > 0 ? su.p5.wsum[warp - 1] : 0);

        float Pi0 = su.p5.sP[0], Pi1 = su.p5.sP[1];
        for (int j = 0; j < 4; j++) {
            if (m[j]) {
                int p = base + j;
                int slot = excl + loc[j];
                int r = p / W_, c = p % W_;
                bool interior = (r >= 4 && r <= H_ - 5 && c >= 4 && c <= W_ - 5);
                float v0 = interior ? Pi0 : g_preds[(b * HW_ + p) * 2];
                float v1 = interior ? Pi1 : g_preds[(b * HW_ + p) * 2 + 1];
                out[(b * HW_ + slot) * 2]            = v0;
                out[(b * HW_ + slot) * 2 + 1]        = v1;
                out[OFF1 + (b * HW_ + slot) * 2]     = (float)r;
                out[OFF1 + (b * HW_ + slot) * 2 + 1] = (float)c;
                out[OFF2 + b * HW_ + slot]           = 1.0f;
            }
        }
    }
}

// ---------------------------------------------------------------------------
// kernel_launch — single persistent node
// ---------------------------------------------------------------------------
extern "C" void kernel_launch(void* const* d_in, const int* in_sizes, int n_in,
                              void* d_out, int out_size) {
    const float* latent = (const float*)d_in[1];
    const int*   mask   = (const int*)  d_in[2];
    const int*   nidx   = (const int*)  d_in[3];
    const int*   ncnt   = (const int*)  d_in[4];
    const float* Wl = (const float*)d_in[5];
    const float* bl = (const float*)d_in[6];
    const float* Wt = (const float*)d_in[7];
    const float* bt = (const float*)d_in[8];
    const float* g1 = (const float*)d_in[9];
    const float* b1g= (const float*)d_in[10];
    const float* Wc = (const float*)d_in[11];
    const float* bc = (const float*)d_in[12];
    const float* Wa = (const float*)d_in[13];
    const float* ba = (const float*)d_in[14];
    const float* W1 = (const float*)d_in[15];
    const float* b1 = (const float*)d_in[16];
    const float* W2 = (const float*)d_in[17];
    const float* b2 = (const float*)d_in[18];

    int nsm = 148;
    cudaDeviceGetAttribute(&nsm, cudaDevAttrMultiProcessorCount, 0);

    kFused<<<nsm, 1024>>>(latent, mask, nidx, ncnt,
                          Wl, bl, Wt, bt, g1, b1g, Wc, bc,
                          Wa, ba, W1, b1, W2, b2,
                          (float*)d_out, out_size / 4);
}